// round 14
// baseline (speedup 1.0000x reference)
#include <cuda_runtime.h>
#include <stdint.h>
#include <math.h>

// HighPassFilter: order-2 IIR biquad, 256 sequences of T=65536 float32.
// R13: concurrency attack. Evidence: R5/R9/R11/R12 all plateau at ncu ~22.2us
// with NOTHING saturated (DRAM<52%, L2 34%, L1 39%, issue 23%) and warps idle
// ~80% -> latency-bound via too few warps (13.8/SM). This round: 4096 warps
// (28/SM, exactly one wave) at minimum work amp: CHUNK=128, WARM=64 (rel_err
// 5.92e-7 validated twice), swizzled conflict-free SMEM, cp.async depth-1
// (NBUF=2, 8KB/warp -> 32KB/block with 4 warps/block -> 7 blocks/SM).

#define T_LEN   65536
#define CHUNK   128     // samples per lane
#define WARM    64      // warm-up samples (validated in R10 & R12)
#define JT      32      // j-tile width
#define NT      ((CHUNK + WARM) / JT)   // 6 tiles per warp
#define NBUF    2       // SMEM ring depth (prefetch distance 1)
#define BLOCK_WARPS 4

#define SUBBYTES  4096              // 32 rows x 128B per tile buffer
#define ITSTEP    (4 * CHUNK)       // 512: global stride per it-step

__device__ __forceinline__ void cp_async16(uint32_t dst_smem, const float* src, int src_size)
{
    asm volatile("cp.async.cg.shared.global [%0], [%1], 16, %2;\n"
                 :: "r"(dst_smem), "l"(src), "r"(src_size));
}

__global__ __launch_bounds__(BLOCK_WARPS * 32, 1)
void biquad_hp_kernel(const float* __restrict__ x, float* __restrict__ y,
                      float b0, float b1, float b2, float na1, float na2)
{
    // [warp][ringbuf][row=chunk][col], XOR-swizzled (quad q of row r -> q^(r&7))
    __shared__ __align__(16) float tile[BLOCK_WARPS][NBUF][32][32];

    const int w    = threadIdx.x >> 5;
    const int lane = threadIdx.x & 31;
    const int g    = lane >> 3;   // chunk subgroup (0..3)
    const int m    = lane & 7;    // 16B slot within a 32-sample row (0..7)

    // 16 warps per sequence, each warp owns 32 contiguous chunks = 4096 samples
    const int gw   = blockIdx.x * BLOCK_WARPS + w;
    const int seq  = gw >> 4;
    const int wseq = gw & 15;

    const long long seqbase = (long long)seq * T_LEN;
    const float* xs = x + seqbase;
    float*       ys = y + seqbase;
    const int warpbase = wseq * (32 * CHUNK);
    const int slotbase = warpbase + g * CHUNK + 4 * m;   // chunk 4it+g, +4m

    uint32_t ringbase;
    asm("{ .reg .u64 t; cvta.to.shared.u64 t, %1; cvt.u32.u64 %0, t; }"
        : "=r"(ringbase) : "l"(&tile[w][0][0][0]));

    // cp.async dst within a tile: row r=4it+g, logical quad m -> phys m^(r&7)
    //   byte = it*512 + g*128 + ((m^g)*16 ^ (it&1 ? 64 : 0))
    const uint32_t off0 = (uint32_t)g * 128u + (uint32_t)((m ^ g) << 4);
    const uint32_t off1 = off0 ^ 64u;
    // store-side float index within a tile, per it
    const int sidx0 = g * 32 + ((m ^ g) << 2);
    const int sidx1 = sidx0 ^ 16;

    float xm1 = 0.f, xm2 = 0.f, ym1 = 0.f, ym2 = 0.f;

    // ---- prologue: prefetch tile 0 (jt = -WARM) into buffer 0
    {
        #pragma unroll
        for (int it = 0; it < 8; ++it) {
            int p = slotbase + it * ITSTEP + (-WARM);
            uint32_t d = ringbase + (uint32_t)(it << 9) + ((it & 1) ? off1 : off0);
            cp_async16(d, xs + (p >= 0 ? p : 0), p >= 0 ? 16 : 0);
        }
        asm volatile("cp.async.commit_group;\n");
    }

    #pragma unroll
    for (int t = 0; t < NT; ++t) {
        const int  jt   = -WARM + t * JT;
        const bool emit = (jt >= 0);
        float* buf = &tile[w][t & 1][0][0];
        float* row = buf + lane * 32;
        const int lq = lane & 7;

        // ---- prefetch tile t+1 into the other buffer, then wait for tile t
        if (t + 1 < NT) {
            const int jn = jt + JT;
            const uint32_t dbase = ringbase + (uint32_t)((t + 1) & 1) * SUBBYTES;
            #pragma unroll
            for (int it = 0; it < 8; ++it) {
                int p = slotbase + it * ITSTEP + jn;
                uint32_t d = dbase + (uint32_t)(it << 9) + ((it & 1) ? off1 : off0);
                cp_async16(d, xs + (p >= 0 ? p : 0), p >= 0 ? 16 : 0);
            }
            asm volatile("cp.async.commit_group;\n");
            asm volatile("cp.async.wait_group 1;\n");   // tile t landed
        } else {
            asm volatile("cp.async.wait_group 0;\n");
        }
        __syncwarp();

        // ---- advance this lane's chunk 32 samples (serial IIR chain);
        //      logical quad j at physical quad j^(lane&7)
        #pragma unroll
        for (int jj = 0; jj < JT; jj += 4) {
            const int colq = ((jj >> 2) ^ lq) << 2;
            float4 xv = *reinterpret_cast<float4*>(&row[colq]);

            float t0 = fmaf(b2, xm2, fmaf(b1, xm1, b0 * xv.x));
            float y0 = fmaf(na2, ym2, fmaf(na1, ym1, t0));
            float t1 = fmaf(b2, xm1, fmaf(b1, xv.x, b0 * xv.y));
            float y1 = fmaf(na2, ym1, fmaf(na1, y0, t1));
            float t2 = fmaf(b2, xv.x, fmaf(b1, xv.y, b0 * xv.z));
            float y2 = fmaf(na2, y0, fmaf(na1, y1, t2));
            float t3 = fmaf(b2, xv.y, fmaf(b1, xv.z, b0 * xv.w));
            float y3 = fmaf(na2, y1, fmaf(na1, y2, t3));

            xm2 = xv.z; xm1 = xv.w;
            ym2 = y2;   ym1 = y3;

            if (emit)
                *reinterpret_cast<float4*>(&row[colq]) =
                    make_float4(y0, y1, y2, y3);
        }
        __syncwarp();

        // ---- coalesced store of computed tile (swizzled SMEM read)
        if (emit) {
            #pragma unroll
            for (int it = 0; it < 8; ++it) {
                int p = slotbase + it * ITSTEP + jt;
                const int si = it * 128 + ((it & 1) ? sidx1 : sidx0);
                *reinterpret_cast<float4*>(ys + p) =
                    *reinterpret_cast<const float4*>(buf + si);
            }
        }
        __syncwarp();
    }
}

extern "C" void kernel_launch(void* const* d_in, const int* in_sizes, int n_in,
                              void* d_out, int out_size)
{
    const float* x = (const float*)d_in[0];
    float*       y = (float*)d_out;

    const int total = in_sizes[0];
    const int nseq  = total / T_LEN;          // 256 for the given shapes

    const double w0    = 2.0 * M_PI * (700.0 / 16000.0);
    const double cw    = cos(w0);
    const double sw    = sin(w0);
    const double q     = 0.70710678;
    const double alpha = sw / (2.0 * q);
    const double a0    = 1.0 + alpha;

    const float b0 = (float)(((1.0 + cw) / 2.0) / a0);
    const float b1 = (float)((-(1.0 + cw)) / a0);
    const float b2 = b0;
    const float a1 = (float)((-2.0 * cw) / a0);
    const float a2 = (float)((1.0 - alpha) / a0);

    const int warps_total = nseq * 16;                 // 16 warps per sequence
    const int grid        = warps_total / BLOCK_WARPS; // 1024 blocks of 128 thr
    biquad_hp_kernel<<<grid, BLOCK_WARPS * 32>>>(x, y, b0, b1, b2, -a1, -a2);
}

// round 15
// speedup vs baseline: 1.2692x; 1.2692x over previous
#include <cuda_runtime.h>
#include <stdint.h>
#include <math.h>

// HighPassFilter: order-2 IIR biquad, 256 sequences of T=65536 float32.
// R15 = R11 memory pipeline (CHUNK=256, WARM=96, XOR-swizzled SMEM, cp.async
// distance-2, 3-buffer ring -- best validated, harness 24.6us) with the
// recurrence reformulated as LOOKAHEAD-4: y[n+k] = T_k + p_k*y1 + q_k*y2,
// T_k = x-only terms (ILP across windows), p/q host-precomputed. State jumps
// 4 samples per 2 chained FMAs -> 2 cyc/sample vs 8. Evidence: all CHUNK=256
// configs plateau at ncu ~22.2us with NOTHING saturated -> per-warp serial
// path (dominated by the 2816-cycle FMA chain) is the binding constraint.

#define T_LEN   65536
#define CHUNK   256     // samples per lane (validated)
#define WARM    96      // warm-up samples (validated)
#define JT      32      // j-tile width
#define NT      ((CHUNK + WARM) / JT)   // 11 tiles per warp
#define NBUF    3       // SMEM ring depth (prefetch distance 2)
#define BLOCK_WARPS 2
#define ROWSTRIDE 32    // exact 128B rows; XOR swizzle for conflict-freedom

#define ROWBYTES  (ROWSTRIDE * 4)       // 128
#define BUFBYTES  (32 * ROWBYTES)       // 4096

__device__ __forceinline__ void cp_async16(uint32_t dst_smem, const float* src, int src_size)
{
    asm volatile("cp.async.cg.shared.global [%0], [%1], 16, %2;\n"
                 :: "r"(dst_smem), "l"(src), "r"(src_size));
}

__global__ __launch_bounds__(BLOCK_WARPS * 32, 1)
void biquad_hp_kernel(const float* __restrict__ x, float* __restrict__ y,
                      float b0, float b1, float b2, float na1, float na2,
                      float pp1, float qq1, float pp2, float qq2,
                      float pp3, float qq3)
{
    // 3-deep ring of swizzled transpose tiles per warp
    __shared__ __align__(16) float tile[BLOCK_WARPS][NBUF][32][ROWSTRIDE];

    const int w    = threadIdx.x >> 5;
    const int lane = threadIdx.x & 31;
    const int g    = lane >> 3;   // chunk subgroup (0..3)
    const int m    = lane & 7;    // 16B slot within a 32-sample row (0..7)

    // 8 warps per sequence, each warp owns 32 contiguous chunks = 8192 samples
    const int gw   = blockIdx.x * BLOCK_WARPS + w;
    const int seq  = gw >> 3;
    const int wseq = gw & 7;

    const long long seqbase = (long long)seq * T_LEN;
    const float* xs = x + seqbase;
    float*       ys = y + seqbase;
    const int warpbase = wseq * (32 * CHUNK);
    const int slotbase = warpbase + g * CHUNK + 4 * m;

    uint32_t ringbase;
    asm("{ .reg .u64 t; cvta.to.shared.u64 t, %1; cvt.u32.u64 %0, t; }"
        : "=r"(ringbase) : "l"(&tile[w][0][0][0]));

    // cp.async dst: row r=4it+g, logical quad m -> phys quad m^(r&7)
    //   byte = it*512 + g*128 + ((m^g)*16 ^ (it&1 ? 64 : 0))
    const uint32_t off0 = (uint32_t)g * 128u + (uint32_t)((m ^ g) << 4);
    const uint32_t off1 = off0 ^ 64u;
    // store-side float index within a buffer, per it
    const int sidx0 = g * 32 + ((m ^ g) << 2);
    const int sidx1 = sidx0 ^ 16;

    float xm1 = 0.f, xm2 = 0.f, ym1 = 0.f, ym2 = 0.f;

    // ---- prologue: prefetch tiles 0 and 1 (separate commit groups)
    #pragma unroll
    for (int pt = 0; pt < 2; ++pt) {
        const int jt = -WARM + pt * JT;
        const uint32_t dbase = ringbase + (uint32_t)pt * BUFBYTES;
        #pragma unroll
        for (int it = 0; it < 8; ++it) {
            int p = slotbase + it * (4 * CHUNK) + jt;
            uint32_t d = dbase + (uint32_t)(it << 9) + ((it & 1) ? off1 : off0);
            cp_async16(d, xs + (p >= 0 ? p : 0), p >= 0 ? 16 : 0);
        }
        asm volatile("cp.async.commit_group;\n");
    }

    #pragma unroll
    for (int t = 0; t < NT; ++t) {
        const int  jt   = -WARM + t * JT;
        const bool emit = (jt >= 0);
        float* buf = &tile[w][t % NBUF][0][0];
        float* row = buf + lane * ROWSTRIDE;
        const int lq = lane & 7;

        // ---- issue tile t+2's cp.async (distance-2 lead), guarded against
        //      pre-sequence reads; always commit a group.
        if (t + 2 < NT) {
            const int jn = jt + 2 * JT;
            const uint32_t dbase = ringbase + (uint32_t)((t + 2) % NBUF) * BUFBYTES;
            #pragma unroll
            for (int it = 0; it < 8; ++it) {
                int p = slotbase + it * (4 * CHUNK) + jn;
                uint32_t d = dbase + (uint32_t)(it << 9) + ((it & 1) ? off1 : off0);
                cp_async16(d, xs + (p >= 0 ? p : 0), p >= 0 ? 16 : 0);
            }
        }
        asm volatile("cp.async.commit_group;\n");
        asm volatile("cp.async.wait_group 2;\n");   // tile t's data landed
        __syncwarp();

        // ---- advance 32 samples via lookahead-4: per 4-sample window the
        //      state (ym1,ym2) advances with ONE pair of chained FMAs.
        #pragma unroll
        for (int jj = 0; jj < JT; jj += 4) {
            const int colq = ((jj >> 2) ^ lq) << 2;
            float4 xv = *reinterpret_cast<float4*>(&row[colq]);

            // x-convolution terms (independent, full ILP)
            float t0 = fmaf(b2, xm2, fmaf(b1, xm1, b0 * xv.x));
            float t1 = fmaf(b2, xm1, fmaf(b1, xv.x, b0 * xv.y));
            float t2 = fmaf(b2, xv.x, fmaf(b1, xv.y, b0 * xv.z));
            float t3 = fmaf(b2, xv.y, fmaf(b1, xv.z, b0 * xv.w));

            // forced-response accumulation within the window (x-only)
            float T1 = fmaf(na1, t0, t1);
            float T2 = fmaf(na1, T1, fmaf(na2, t0, t2));
            float T3 = fmaf(na1, T2, fmaf(na2, T1, t3));

            // outputs from (ym1, ym2) -- all four independent
            float o0 = fmaf(na2, ym2, fmaf(na1, ym1, t0));
            float o1 = fmaf(qq1, ym2, fmaf(pp1, ym1, T1));
            float o2 = fmaf(qq2, ym2, fmaf(pp2, ym1, T2));
            float o3 = fmaf(qq3, ym2, fmaf(pp3, ym1, T3));

            xm2 = xv.z; xm1 = xv.w;
            ym2 = o2;   ym1 = o3;

            if (emit)
                *reinterpret_cast<float4*>(&row[colq]) =
                    make_float4(o0, o1, o2, o3);
        }
        __syncwarp();

        // ---- coalesced store of computed tile (swizzled SMEM read)
        if (emit) {
            #pragma unroll
            for (int it = 0; it < 8; ++it) {
                int p = slotbase + it * (4 * CHUNK) + jt;
                const int si = it * 128 + ((it & 1) ? sidx1 : sidx0);
                *reinterpret_cast<float4*>(ys + p) =
                    *reinterpret_cast<const float4*>(buf + si);
            }
        }
        __syncwarp();
    }
}

extern "C" void kernel_launch(void* const* d_in, const int* in_sizes, int n_in,
                              void* d_out, int out_size)
{
    const float* x = (const float*)d_in[0];
    float*       y = (float*)d_out;

    const int total = in_sizes[0];
    const int nseq  = total / T_LEN;          // 256 for the given shapes

    const double w0    = 2.0 * M_PI * (700.0 / 16000.0);
    const double cw    = cos(w0);
    const double sw    = sin(w0);
    const double q     = 0.70710678;
    const double alpha = sw / (2.0 * q);
    const double a0    = 1.0 + alpha;

    const double b0d = ((1.0 + cw) / 2.0) / a0;
    const double b1d = (-(1.0 + cw)) / a0;
    const double a1d = (-2.0 * cw) / a0;
    const double a2d = (1.0 - alpha) / a0;

    // lookahead coefficients: y[n+k] = T_k + p_k*y[n-1] + q_k*y[n-2]
    const double n1 = -a1d, n2 = -a2d;          // p0 = n1, q0 = n2
    const double p1 = n1 * n1 + n2, q1 = n1 * n2;
    const double p2 = n1 * p1 + n2 * n1, q2 = n1 * q1 + n2 * n2;
    const double p3 = n1 * p2 + n2 * p1, q3 = n1 * q2 + n2 * q1;

    const int warps_total = nseq * 8;                  // 8 warps per sequence
    const int grid        = warps_total / BLOCK_WARPS; // 1024 blocks
    biquad_hp_kernel<<<grid, BLOCK_WARPS * 32>>>(
        x, y,
        (float)b0d, (float)b1d, (float)b0d,
        (float)n1, (float)n2,
        (float)p1, (float)q1, (float)p2, (float)q2, (float)p3, (float)q3);
}